// round 11
// baseline (speedup 1.0000x reference)
#include <cuda_runtime.h>
#include <cuda_bf16.h>
#include <math.h>
#include <stdint.h>

// Problem constants
#define BATCH  4
#define DIM    192
#define HH     128
#define WW     128
#define HW     16384            // 128*128
#define HEADS  4
#define CH     48               // DIM / HEADS
#define MQKV   576              // 3*DIM
#define KDIM   192              // reduction dim of 1x1 convs
#define BHN    16               // BATCH*HEADS

typedef unsigned long long u64;

// ---------------- warp-MMA helpers (baseline ISA, no arch suffix) ----------
__device__ __forceinline__ uint32_t smem_u32(const void* p) {
    uint32_t a;
    asm("{ .reg .u64 t; cvta.to.shared.u64 t, %1; cvt.u32.u64 %0, t; }"
        : "=r"(a) : "l"(p));
    return a;
}
__device__ __forceinline__ void ldm_x4(uint32_t r[4], uint32_t addr) {
    asm volatile("ldmatrix.sync.aligned.m8n8.x4.shared.b16 {%0,%1,%2,%3}, [%4];"
                 : "=r"(r[0]), "=r"(r[1]), "=r"(r[2]), "=r"(r[3]) : "r"(addr));
}
__device__ __forceinline__ void ldm_x2(uint32_t r[2], uint32_t addr) {
    asm volatile("ldmatrix.sync.aligned.m8n8.x2.shared.b16 {%0,%1}, [%2];"
                 : "=r"(r[0]), "=r"(r[1]) : "r"(addr));
}
__device__ __forceinline__ void ldm_x2t(uint32_t r[2], uint32_t addr) {
    asm volatile("ldmatrix.sync.aligned.m8n8.x2.trans.shared.b16 {%0,%1}, [%2];"
                 : "=r"(r[0]), "=r"(r[1]) : "r"(addr));
}
__device__ __forceinline__ void mma_bf16(float c[4], const uint32_t a[4],
                                         const uint32_t b[2]) {
    asm volatile(
        "mma.sync.aligned.m16n8k16.row.col.f32.bf16.bf16.f32 "
        "{%0,%1,%2,%3}, {%4,%5,%6,%7}, {%8,%9}, {%0,%1,%2,%3};"
        : "+f"(c[0]), "+f"(c[1]), "+f"(c[2]), "+f"(c[3])
        : "r"(a[0]), "r"(a[1]), "r"(a[2]), "r"(a[3]), "r"(b[0]), "r"(b[1]));
}
__device__ __forceinline__ void bsplit4(const float4 v, u64& hp, u64& lp) {
    __nv_bfloat16 h[4], l[4];
    h[0] = __float2bfloat16(v.x); l[0] = __float2bfloat16(v.x - __bfloat162float(h[0]));
    h[1] = __float2bfloat16(v.y); l[1] = __float2bfloat16(v.y - __bfloat162float(h[1]));
    h[2] = __float2bfloat16(v.z); l[2] = __float2bfloat16(v.z - __bfloat162float(h[2]));
    h[3] = __float2bfloat16(v.w); l[3] = __float2bfloat16(v.w - __bfloat162float(h[3]));
    hp = *(const u64*)h;
    lp = *(const u64*)l;
}

// ---------------- scratch (device globals; no allocation allowed) ----------
__device__ __align__(16) float g_qkv[(size_t)BATCH * MQKV * HW];  // conv1x1 qkv output
__device__ __align__(16) float g_dw [(size_t)BATCH * MQKV * HW];  // dwconv output (v only)
__device__ __align__(16) float g_S   [BHN * CH * CH];             // q.k^T partial sums
__device__ __align__(16) float g_norm[BHN * 96];                  // sumsq: q rows then k rows
__device__ __align__(16) float g_comb[BHN * CH * CH];             // combined attention weights
// bf16 hi/lo split weights
__device__ __align__(16) __nv_bfloat16 g_wqh[MQKV * KDIM];
__device__ __align__(16) __nv_bfloat16 g_wql[MQKV * KDIM];
__device__ __align__(16) __nv_bfloat16 g_weh[BATCH * DIM * KDIM]; // W_eff hi (per batch)
__device__ __align__(16) __nv_bfloat16 g_wel[BATCH * DIM * KDIM]; // W_eff lo

// ---------------- weight split + zero accumulators (one launch) ------------
__global__ void w_split(const float* __restrict__ wq)
{
    const int i = blockIdx.x * 256 + threadIdx.x;
    if (i < MQKV * KDIM) {
        const float x = wq[i];
        const __nv_bfloat16 h = __float2bfloat16(x);
        g_wqh[i] = h;
        g_wql[i] = __float2bfloat16(x - __bfloat162float(h));
    }
    if (i < BHN * CH * CH) g_S[i] = 0.f;
    if (i < BHN * 96)      g_norm[i] = 0.f;
}

// ---------------- tensor-core conv1x1 via mma.sync bf16 3-product split ----
#define GA_STRIDE 56
#define GB_STRIDE 136
#define GS_AH 0
#define GS_AL (128 * GA_STRIDE)                 // bf16 idx
#define GS_BH (2 * 128 * GA_STRIDE)
#define GS_BL (2 * 128 * GA_STRIDE + 48 * GB_STRIDE)
#define G_SMEM_BF16 (2 * 128 * GA_STRIDE + 2 * 48 * GB_STRIDE)
#define G_SMEM_BYTES (G_SMEM_BF16 * 2)          // 54784

__global__ __launch_bounds__(256) void gemm_mma(
    const __nv_bfloat16* __restrict__ Wh, const __nv_bfloat16* __restrict__ Wl,
    const float* __restrict__ X, float* __restrict__ Y, int M,
    long wstride, long xstride, long ystride)
{
    extern __shared__ __align__(16) __nv_bfloat16 sm[];
    __nv_bfloat16* sAh = sm + GS_AH;
    __nv_bfloat16* sAl = sm + GS_AL;
    __nv_bfloat16* sBh = sm + GS_BH;
    __nv_bfloat16* sBl = sm + GS_BL;
    const uint32_t uAh = smem_u32(sAh), uAl = smem_u32(sAl);
    const uint32_t uBh = smem_u32(sBh), uBl = smem_u32(sBl);

    const int tid  = threadIdx.x;
    const int lane = tid & 31;
    const int wid  = tid >> 5;
    const int wm   = (wid >> 2) * 64;     // warp m offset
    const int wn   = (wid & 3) * 32;      // warp n offset
    const int b    = blockIdx.z;
    const int m0   = blockIdx.y * 128;
    const int p0   = blockIdx.x * 128;
    const __nv_bfloat16* Whb = Wh + (size_t)b * wstride;
    const __nv_bfloat16* Wlb = Wl + (size_t)b * wstride;
    const float* Xb = X + (size_t)b * xstride;
    float*       Yb = Y + (size_t)b * ystride;

    float acc[4][4][4];
    #pragma unroll
    for (int mi = 0; mi < 4; ++mi)
        #pragma unroll
        for (int ni = 0; ni < 4; ++ni)
            #pragma unroll
            for (int r = 0; r < 4; ++r) acc[mi][ni][r] = 0.f;

    for (int kt = 0; kt < 4; ++kt) {
        const int k0 = kt * 48;
        // ---- A tile: pre-split bf16 weights, rows m0..m0+127, k0..k0+47 ----
        #pragma unroll
        for (int i = 0; i < 6; ++i) {                 // 1536 u64 chunks
            const int c   = tid + 256 * i;
            const int row = c / 12;
            const int cc  = c % 12;
            const int m   = m0 + row;
            u64 vh = 0ull, vl = 0ull;
            if (m < M) {
                vh = *(const u64*)(Whb + (size_t)m * KDIM + k0 + cc * 4);
                vl = *(const u64*)(Wlb + (size_t)m * KDIM + k0 + cc * 4);
            }
            *(u64*)(sAh + row * GA_STRIDE + cc * 4) = vh;
            *(u64*)(sAl + row * GA_STRIDE + cc * 4) = vl;
        }
        // ---- B tile: X fp32 -> bf16 hi/lo, stored [k][n] (no transpose) ----
        #pragma unroll
        for (int i = 0; i < 6; ++i) {                 // 48 rows x 32 float4
            const int c  = tid + 256 * i;
            const int kk = c >> 5;
            const int p4 = (c & 31) * 4;
            const float4 v = *(const float4*)(Xb + (size_t)(k0 + kk) * HW + p0 + p4);
            u64 hp, lp;
            bsplit4(v, hp, lp);
            *(u64*)(sBh + kk * GB_STRIDE + p4) = hp;
            *(u64*)(sBl + kk * GB_STRIDE + p4) = lp;
        }
        __syncthreads();

        #pragma unroll
        for (int ks = 0; ks < 3; ++ks) {
            const int kk0 = ks * 16;
            uint32_t bh[4][2], bl[4][2];
            const int brow = kk0 + (lane & 15);
            #pragma unroll
            for (int ni = 0; ni < 4; ++ni) {
                const uint32_t boffB = (uint32_t)(brow * GB_STRIDE + wn + ni * 8) * 2;
                ldm_x2t(bh[ni], uBh + boffB);
                ldm_x2t(bl[ni], uBl + boffB);
            }
            const int arow = wm + (lane & 15);
            const uint32_t akcol = (uint32_t)(kk0 + ((lane >> 4) << 3));
            #pragma unroll
            for (int mi = 0; mi < 4; ++mi) {
                uint32_t ah[4], al[4];
                const uint32_t aoff = (uint32_t)((arow + mi * 16) * GA_STRIDE + akcol) * 2;
                ldm_x4(ah, uAh + aoff);
                ldm_x4(al, uAl + aoff);
                #pragma unroll
                for (int ni = 0; ni < 4; ++ni) {
                    mma_bf16(acc[mi][ni], ah, bh[ni]);   // Ah*Bh
                    mma_bf16(acc[mi][ni], ah, bl[ni]);   // Ah*Bl
                    mma_bf16(acc[mi][ni], al, bh[ni]);   // Al*Bh
                }
            }
        }
        __syncthreads();
    }

    const int g  = lane >> 2;
    const int tg = lane & 3;
    #pragma unroll
    for (int mi = 0; mi < 4; ++mi) {
        #pragma unroll
        for (int ni = 0; ni < 4; ++ni) {
            const int m = m0 + wm + mi * 16 + g;
            const int p = p0 + wn + ni * 8 + tg * 2;
            if (m < M)
                *(float2*)(Yb + (size_t)m * HW + p) =
                    make_float2(acc[mi][ni][0], acc[mi][ni][1]);
            if (m + 8 < M)
                *(float2*)(Yb + (size_t)(m + 8) * HW + p) =
                    make_float2(acc[mi][ni][2], acc[mi][ni][3]);
        }
    }
}

// ---------------- depthwise 3x3, pad 1, smem-tiled (v channels only) -------
#define DW_TH 16
__global__ __launch_bounds__(256) void dwconv3x3_v(
    const float* __restrict__ in, const float* __restrict__ wdw,
    float* __restrict__ out)
{
    const int bc = blockIdx.y;                  // 0..BATCH*DIM-1
    const int h0 = blockIdx.x * DW_TH;
    const int b  = bc / DIM;
    const int cd = bc % DIM;
    const int gc = 2 * DIM + cd;                // v channel in qkv layout
    const float* base = in + ((size_t)b * MQKV + gc) * HW;
    float*       ob0  = out + ((size_t)b * MQKV + gc) * HW;
    const int tid = threadIdx.x;

    __shared__ __align__(16) float st[DW_TH + 2][132];
    __shared__ float wsh[9];
    if (tid < 9) wsh[tid] = wdw[gc * 9 + tid];

    #pragma unroll
    for (int idx = tid; idx < 18 * 32; idx += 256) {
        const int r  = idx >> 5;
        const int c4 = (idx & 31) << 2;
        const int gh = h0 - 1 + r;
        float4 v = make_float4(0.f, 0.f, 0.f, 0.f);
        if (gh >= 0 && gh < HH) v = *(const float4*)(base + (size_t)gh * WW + c4);
        *(float4*)&st[r][c4] = v;
    }
    __syncthreads();

    const int w     = tid & 127;
    const int strip = tid >> 7;                 // 0 or 1
    const int hb    = strip * 8;                // local pixel rows hb..hb+7
    const bool wl = (w > 0), wr = (w < 127);
    const float w00 = wsh[0], w01 = wsh[1], w02 = wsh[2];
    const float w10 = wsh[3], w11 = wsh[4], w12 = wsh[5];
    const float w20 = wsh[6], w21 = wsh[7], w22 = wsh[8];

    float l0 = wl ? st[hb][w - 1] : 0.f;
    float m0 = st[hb][w];
    float r0 = wr ? st[hb][w + 1] : 0.f;
    float l1 = wl ? st[hb + 1][w - 1] : 0.f;
    float m1 = st[hb + 1][w];
    float r1 = wr ? st[hb + 1][w + 1] : 0.f;

    float* ob = ob0 + (size_t)(h0 + hb) * WW + w;
    #pragma unroll
    for (int rr = 0; rr < 8; ++rr) {
        const int sr = hb + rr + 2;
        const float l2 = wl ? st[sr][w - 1] : 0.f;
        const float m2 = st[sr][w];
        const float r2 = wr ? st[sr][w + 1] : 0.f;
        float s = w00 * l0;
        s = fmaf(w01, m0, s); s = fmaf(w02, r0, s);
        s = fmaf(w10, l1, s); s = fmaf(w11, m1, s); s = fmaf(w12, r1, s);
        s = fmaf(w20, l2, s); s = fmaf(w21, m2, s); s = fmaf(w22, r2, s);
        ob[(size_t)rr * WW] = s;
        l0 = l1; m0 = m1; r0 = r1;
        l1 = l2; m1 = m2; r1 = r2;
    }
}

// ---------------- fused dwconv(q,k) + S = q.k^T + norms --------------------
// CTA = (bh, 4-image-row chunk = 512 px). For each 64-px tile (row, half),
// every thread computes the 3x3 depthwise conv for 6 channel-rows x 4 px
// directly from g_qkv (register window; lateral neighbors via shfl, half-
// boundary columns via scalar loads, image borders zero), splits to bf16
// hi/lo in smem, then 6 MMA warps accumulate the 48x48 q.k^T block.
#define AP_STRIDE 72
__global__ __launch_bounds__(256) void dwqk_gram(const float* __restrict__ wdw)
{
    __shared__ __align__(16) __nv_bfloat16 sZh[96 * AP_STRIDE];
    __shared__ __align__(16) __nv_bfloat16 sZl[96 * AP_STRIDE];
    __shared__ float swd[96][9];
    const uint32_t uZh = smem_u32(sZh), uZl = smem_u32(sZl);

    const int tid  = threadIdx.x;
    const int lane = tid & 31;
    const int wid  = tid >> 5;
    const int l16  = tid & 15;
    const int rg   = tid >> 4;              // 0..15 channel row-group
    const int wm   = (wid >> 1) * 16;       // 0,16,32 (warps 0-5)
    const int wn   = (wid & 1) * 24;        // 0,24
    const int bh   = blockIdx.x;
    const int b    = bh >> 2;
    const int hh   = bh & 3;
    const int h0   = blockIdx.y * 4;        // 4 image rows per CTA

    // channel base pointers (q rows 0-47, k rows 48-95) + dw weights to smem
    const float* chb[6];
    #pragma unroll
    for (int i = 0; i < 6; ++i) {
        const int c  = rg + 16 * i;
        const int gc = (c < 48) ? (hh * CH + c) : (DIM + hh * CH + (c - 48));
        chb[i] = g_qkv + ((size_t)b * MQKV + gc) * HW;
    }
    for (int j = tid; j < 96 * 9; j += 256) {
        const int c  = j / 9;
        const int gc = (c < 48) ? (hh * CH + c) : (DIM + hh * CH + (c - 48));
        swd[c][j % 9] = wdw[gc * 9 + (j % 9)];
    }
    __syncthreads();

    float acc[3][4];
    #pragma unroll
    for (int ni = 0; ni < 3; ++ni)
        #pragma unroll
        for (int r = 0; r < 4; ++r) acc[ni][r] = 0.f;
    float sq[6];
    #pragma unroll
    for (int i = 0; i < 6; ++i) sq[i] = 0.f;

    for (int t = 0; t < 8; ++t) {
        const int h    = h0 + (t >> 1);
        const int col0 = (t & 1) * 64;
        const int colt = col0 + l16 * 4;

        #pragma unroll
        for (int i = 0; i < 6; ++i) {
            const int row = rg + 16 * i;
            float r0 = 0.f, r1 = 0.f, r2 = 0.f, r3 = 0.f;
            #pragma unroll
            for (int dy = 0; dy < 3; ++dy) {
                const int gh = h - 1 + dy;
                const bool okr = (gh >= 0) && (gh < HH);
                const float* rp = chb[i] + (size_t)gh * WW + colt;
                float4 v = make_float4(0.f, 0.f, 0.f, 0.f);
                if (okr) v = *(const float4*)rp;
                float lft = __shfl_up_sync(0xffffffffu, v.w, 1);
                float rgt = __shfl_down_sync(0xffffffffu, v.x, 1);
                if (l16 == 0)  lft = (okr && col0 == 64) ? rp[-1] : 0.f;
                if (l16 == 15) rgt = (okr && col0 == 0)  ? rp[4]  : 0.f;
                const float w0 = swd[row][dy * 3 + 0];
                const float w1 = swd[row][dy * 3 + 1];
                const float w2 = swd[row][dy * 3 + 2];
                r0 = fmaf(w0, lft, fmaf(w1, v.x, fmaf(w2, v.y, r0)));
                r1 = fmaf(w0, v.x, fmaf(w1, v.y, fmaf(w2, v.z, r1)));
                r2 = fmaf(w0, v.y, fmaf(w1, v.z, fmaf(w2, v.w, r2)));
                r3 = fmaf(w0, v.z, fmaf(w1, v.w, fmaf(w2, rgt, r3)));
            }
            sq[i] = fmaf(r0, r0, sq[i]);
            sq[i] = fmaf(r1, r1, sq[i]);
            sq[i] = fmaf(r2, r2, sq[i]);
            sq[i] = fmaf(r3, r3, sq[i]);
            u64 hp, lp;
            bsplit4(make_float4(r0, r1, r2, r3), hp, lp);
            *(u64*)(sZh + row * AP_STRIDE + l16 * 4) = hp;
            *(u64*)(sZl + row * AP_STRIDE + l16 * 4) = lp;
        }
        __syncthreads();

        if (wid < 6) {
            #pragma unroll
            for (int ks = 0; ks < 4; ++ks) {
                const int kk0 = ks * 16;
                const int arow = wm + (lane & 15);
                const uint32_t akcol = (uint32_t)(kk0 + ((lane >> 4) << 3));
                uint32_t ah[4], al[4];
                const uint32_t aoff = (uint32_t)(arow * AP_STRIDE + akcol) * 2;
                ldm_x4(ah, uZh + aoff);
                ldm_x4(al, uZl + aoff);
                const int bl16 = lane & 15;
                const int bn   = bl16 & 7;
                const int bk   = kk0 + ((bl16 >> 3) << 3);
                #pragma unroll
                for (int ni = 0; ni < 3; ++ni) {
                    uint32_t bfh[2], bfl[2];
                    const uint32_t boff =
                        (uint32_t)((48 + wn + ni * 8 + bn) * AP_STRIDE + bk) * 2;
                    ldm_x2(bfh, uZh + boff);
                    ldm_x2(bfl, uZl + boff);
                    mma_bf16(acc[ni], ah, bfh);
                    mma_bf16(acc[ni], ah, bfl);
                    mma_bf16(acc[ni], al, bfh);
                }
            }
        }
        __syncthreads();
    }

    // norms: 16 lanes per channel row -> butterfly reduce, one atomic each
    #pragma unroll
    for (int i = 0; i < 6; ++i) {
        float s = sq[i];
        s += __shfl_xor_sync(0xffffffffu, s, 1);
        s += __shfl_xor_sync(0xffffffffu, s, 2);
        s += __shfl_xor_sync(0xffffffffu, s, 4);
        s += __shfl_xor_sync(0xffffffffu, s, 8);
        if (l16 == 0) atomicAdd(&g_norm[bh * 96 + rg + 16 * i], s);
    }

    if (wid < 6) {
        float* Sp = g_S + (size_t)bh * CH * CH;
        const int g  = lane >> 2;
        const int tg = lane & 3;
        #pragma unroll
        for (int ni = 0; ni < 3; ++ni) {
            const int m = wm + g;
            const int n = wn + ni * 8 + tg * 2;
            atomicAdd(&Sp[m * CH + n],           acc[ni][0]);
            atomicAdd(&Sp[m * CH + n + 1],       acc[ni][1]);
            atomicAdd(&Sp[(m + 8) * CH + n],     acc[ni][2]);
            atomicAdd(&Sp[(m + 8) * CH + n + 1], acc[ni][3]);
        }
    }
}

// ---------------- finalize: normalize, per-row topk/softmax, combine -------
// k values: int(48*rate) in IEEE double: {24, 32 (round-to-even), 36, 38}
__global__ void finalize_comb(const float* __restrict__ temperature,
                              const float* __restrict__ attn_w)
{
    const int bh = blockIdx.x;
    const int hh = bh & 3;
    const int i  = threadIdx.x;
    if (i >= CH) return;

    float a[CH];
    const float nq = fmaxf(sqrtf(g_norm[bh * 96 + i]), 1e-12f);
    const float tmp = temperature[hh];
    for (int j = 0; j < CH; ++j) {
        const float nk = fmaxf(sqrtf(g_norm[bh * 96 + 48 + j]), 1e-12f);
        a[j] = g_S[bh * CH * CH + i * CH + j] * tmp / (nq * nk);
    }

    int rank[CH];
    for (int j = 0; j < CH; ++j) {
        int r = 0;
        for (int l = 0; l < CH; ++l)
            if (a[l] > a[j] || (a[l] == a[j] && l < j)) r++;
        rank[j] = r;
    }

    float comb[CH];
    for (int j = 0; j < CH; ++j) comb[j] = 0.f;

    const int kvals[4] = {24, 32, 36, 38};
    for (int r = 0; r < 4; ++r) {
        const int kv = kvals[r];
        float m = -INFINITY;
        for (int j = 0; j < CH; ++j)
            if (rank[j] < kv) m = fmaxf(m, a[j]);
        float e[CH];
        float ssum = 0.f;
        for (int j = 0; j < CH; ++j) {
            e[j] = (rank[j] < kv) ? expf(a[j] - m) : 0.f;
            ssum += e[j];
        }
        const float wgt = attn_w[r] / ssum;
        for (int j = 0; j < CH; ++j) comb[j] = fmaf(e[j], wgt, comb[j]);
    }

    for (int j = 0; j < CH; ++j)
        g_comb[bh * CH * CH + i * CH + j] = comb[j];
}

// ---------------- W_eff = W_proj . blockdiag(comb), split to bf16 hi/lo ----
__global__ __launch_bounds__(192) void weff_compute(const float* __restrict__ wproj)
{
    const int bh = blockIdx.x;          // 0..15
    const int b  = bh >> 2;
    const int hh = bh & 3;
    const int o  = threadIdx.x;         // 0..191

    __shared__ float cs[CH][CH];
    for (int l = o; l < CH * CH; l += 192)
        cs[l / CH][l % CH] = g_comb[bh * CH * CH + l];
    __syncthreads();

    float wr[CH];
    #pragma unroll
    for (int c = 0; c < CH; ++c) wr[c] = wproj[o * KDIM + hh * CH + c];

    __nv_bfloat16* eh = g_weh + ((size_t)b * DIM + o) * KDIM + hh * CH;
    __nv_bfloat16* el = g_wel + ((size_t)b * DIM + o) * KDIM + hh * CH;
    for (int d = 0; d < CH; ++d) {
        float s = 0.f;
        #pragma unroll
        for (int c = 0; c < CH; ++c) s = fmaf(wr[c], cs[c][d], s);
        const __nv_bfloat16 h = __float2bfloat16(s);
        eh[d] = h;
        el[d] = __float2bfloat16(s - __bfloat162float(h));
    }
}

// ---------------- launch ----------------------------------------------------
extern "C" void kernel_launch(void* const* d_in, const int* in_sizes, int n_in,
                              void* d_out, int out_size)
{
    const float* x           = (const float*)d_in[0];  // [4,192,128,128]
    const float* w_qkv       = (const float*)d_in[1];  // [576,192]
    const float* w_dw        = (const float*)d_in[2];  // [576,9]
    const float* w_proj      = (const float*)d_in[3];  // [192,192]
    const float* temperature = (const float*)d_in[4];  // [4]
    const float* attn_w      = (const float*)d_in[5];  // [4]
    float* out = (float*)d_out;

    float* qkv; cudaGetSymbolAddress((void**)&qkv, g_qkv);
    float* dw;  cudaGetSymbolAddress((void**)&dw,  g_dw);
    __nv_bfloat16* wqh; cudaGetSymbolAddress((void**)&wqh, g_wqh);
    __nv_bfloat16* wql; cudaGetSymbolAddress((void**)&wql, g_wql);
    __nv_bfloat16* weh; cudaGetSymbolAddress((void**)&weh, g_weh);
    __nv_bfloat16* wel; cudaGetSymbolAddress((void**)&wel, g_wel);

    static bool attr_set = false;
    if (!attr_set) {
        cudaFuncSetAttribute(gemm_mma,
                             cudaFuncAttributeMaxDynamicSharedMemorySize,
                             G_SMEM_BYTES);
        attr_set = true;
    }

    // 0. split qkv weights into bf16 hi/lo + zero S/norm accumulators
    w_split<<<(MQKV * KDIM + 255) / 256, 256>>>(w_qkv);

    // 1. qkv = w_qkv @ x  (tensor cores, shared weights across batch)
    gemm_mma<<<dim3(HW / 128, (MQKV + 127) / 128, BATCH), 256, G_SMEM_BYTES>>>(
        wqh, wql, x, qkv, MQKV, 0, (long)KDIM * HW, (long)MQKV * HW);

    // 2. depthwise 3x3 for v channels only (q,k fused into dwqk_gram)
    dwconv3x3_v<<<dim3(HH / DW_TH, BATCH * DIM), 256>>>(qkv, w_dw, dw);

    // 3. fused dwconv(q,k) + S = q.k^T + norms
    dwqk_gram<<<dim3(BHN, 32), 256>>>(w_dw);

    // 4. combined attention weights (topk + softmax + weighted sum)
    finalize_comb<<<BHN, 64>>>(temperature, attn_w);

    // 5. W_eff[b] = W_proj . blockdiag(comb_b)  (fuses attn_apply into proj)
    weff_compute<<<BHN, 192>>>(w_proj);

    // 6. out = W_eff[b] @ v  (tensor cores, per-batch weights, v from g_dw)
    gemm_mma<<<dim3(HW / 128, (DIM + 127) / 128, BATCH), 256, G_SMEM_BYTES>>>(
        weh, wel, dw + (size_t)2 * DIM * HW, out, DIM,
        (long)DIM * KDIM, (long)MQKV * HW, (long)DIM * HW);
}

// round 12
// speedup vs baseline: 1.1800x; 1.1800x over previous
#include <cuda_runtime.h>
#include <cuda_bf16.h>
#include <math.h>
#include <stdint.h>

// Problem constants
#define BATCH  4
#define DIM    192
#define HH     128
#define WW     128
#define HW     16384            // 128*128
#define HEADS  4
#define CH     48               // DIM / HEADS
#define MQKV   576              // 3*DIM
#define KDIM   192              // reduction dim of 1x1 convs
#define BHN    16               // BATCH*HEADS

typedef unsigned long long u64;

// ---------------- warp-MMA helpers (baseline ISA, no arch suffix) ----------
__device__ __forceinline__ uint32_t smem_u32(const void* p) {
    uint32_t a;
    asm("{ .reg .u64 t; cvta.to.shared.u64 t, %1; cvt.u32.u64 %0, t; }"
        : "=r"(a) : "l"(p));
    return a;
}
__device__ __forceinline__ void ldm_x4(uint32_t r[4], uint32_t addr) {
    asm volatile("ldmatrix.sync.aligned.m8n8.x4.shared.b16 {%0,%1,%2,%3}, [%4];"
                 : "=r"(r[0]), "=r"(r[1]), "=r"(r[2]), "=r"(r[3]) : "r"(addr));
}
__device__ __forceinline__ void ldm_x2(uint32_t r[2], uint32_t addr) {
    asm volatile("ldmatrix.sync.aligned.m8n8.x2.shared.b16 {%0,%1}, [%2];"
                 : "=r"(r[0]), "=r"(r[1]) : "r"(addr));
}
__device__ __forceinline__ void ldm_x2t(uint32_t r[2], uint32_t addr) {
    asm volatile("ldmatrix.sync.aligned.m8n8.x2.trans.shared.b16 {%0,%1}, [%2];"
                 : "=r"(r[0]), "=r"(r[1]) : "r"(addr));
}
__device__ __forceinline__ void mma_bf16(float c[4], const uint32_t a[4],
                                         const uint32_t b[2]) {
    asm volatile(
        "mma.sync.aligned.m16n8k16.row.col.f32.bf16.bf16.f32 "
        "{%0,%1,%2,%3}, {%4,%5,%6,%7}, {%8,%9}, {%0,%1,%2,%3};"
        : "+f"(c[0]), "+f"(c[1]), "+f"(c[2]), "+f"(c[3])
        : "r"(a[0]), "r"(a[1]), "r"(a[2]), "r"(a[3]), "r"(b[0]), "r"(b[1]));
}
__device__ __forceinline__ void bsplit4(const float4 v, u64& hp, u64& lp) {
    __nv_bfloat16 h[4], l[4];
    h[0] = __float2bfloat16(v.x); l[0] = __float2bfloat16(v.x - __bfloat162float(h[0]));
    h[1] = __float2bfloat16(v.y); l[1] = __float2bfloat16(v.y - __bfloat162float(h[1]));
    h[2] = __float2bfloat16(v.z); l[2] = __float2bfloat16(v.z - __bfloat162float(h[2]));
    h[3] = __float2bfloat16(v.w); l[3] = __float2bfloat16(v.w - __bfloat162float(h[3]));
    hp = *(const u64*)h;
    lp = *(const u64*)l;
}

// ---------------- scratch (device globals; no allocation allowed) ----------
__device__ __align__(16) float g_qkv[(size_t)BATCH * MQKV * HW];  // conv1x1 qkv output
__device__ __align__(16) float g_dw [(size_t)BATCH * MQKV * HW];  // after depthwise 3x3
__device__ __align__(16) float g_S   [BHN * CH * CH];             // q.k^T partial sums
__device__ __align__(16) float g_norm[BHN * 96];                  // sumsq: q rows then k rows
__device__ __align__(16) float g_comb[BHN * CH * CH];             // combined attention weights
// bf16 hi/lo split weights
__device__ __align__(16) __nv_bfloat16 g_wqh[MQKV * KDIM];
__device__ __align__(16) __nv_bfloat16 g_wql[MQKV * KDIM];
__device__ __align__(16) __nv_bfloat16 g_weh[BATCH * DIM * KDIM]; // W_eff hi (per batch)
__device__ __align__(16) __nv_bfloat16 g_wel[BATCH * DIM * KDIM]; // W_eff lo

// ---------------- weight split + zero accumulators (one launch) ------------
__global__ void w_split(const float* __restrict__ wq)
{
    const int i = blockIdx.x * 256 + threadIdx.x;
    if (i < MQKV * KDIM) {
        const float x = wq[i];
        const __nv_bfloat16 h = __float2bfloat16(x);
        g_wqh[i] = h;
        g_wql[i] = __float2bfloat16(x - __bfloat162float(h));
    }
    if (i < BHN * CH * CH) g_S[i] = 0.f;
    if (i < BHN * 96)      g_norm[i] = 0.f;
}

// ---------------- tensor-core conv1x1 via mma.sync bf16 3-product split ----
// Y[b][m][p] = sum_k W_b[m][k] X_b[k][p].
// CTA owns a 128-pixel block; loads/converts the FULL-K B tile (192x128,
// hi/lo) ONCE, then loops over all m-tiles, staging the small A (weights)
// tile per (mt, kt) from L2.  8 warps (2x4), warp tile 64x32.
#define GA_STRIDE 56
#define GB_STRIDE 136
#define SM_BH 0
#define SM_BL (192 * GB_STRIDE)                     // 26112
#define SM_AH (2 * 192 * GB_STRIDE)                 // 52224
#define SM_AL (2 * 192 * GB_STRIDE + 128 * GA_STRIDE)
#define G_SMEM_BF16 (2 * 192 * GB_STRIDE + 2 * 128 * GA_STRIDE)
#define G_SMEM_BYTES (G_SMEM_BF16 * 2)              // 133120

__global__ __launch_bounds__(256) void gemm_mma(
    const __nv_bfloat16* __restrict__ Wh, const __nv_bfloat16* __restrict__ Wl,
    const float* __restrict__ X, float* __restrict__ Y, int M, int nmt,
    long wstride, long xstride, long ystride)
{
    extern __shared__ __align__(16) __nv_bfloat16 sm[];
    __nv_bfloat16* sBh = sm + SM_BH;
    __nv_bfloat16* sBl = sm + SM_BL;
    __nv_bfloat16* sAh = sm + SM_AH;
    __nv_bfloat16* sAl = sm + SM_AL;
    const uint32_t uBh = smem_u32(sBh), uBl = smem_u32(sBl);
    const uint32_t uAh = smem_u32(sAh), uAl = smem_u32(sAl);

    const int tid  = threadIdx.x;
    const int lane = tid & 31;
    const int wid  = tid >> 5;
    const int wm   = (wid >> 2) * 64;     // warp m offset
    const int wn   = (wid & 3) * 32;      // warp n offset
    const int b    = blockIdx.z;
    const int p0   = blockIdx.x * 128;
    const __nv_bfloat16* Whb = Wh + (size_t)b * wstride;
    const __nv_bfloat16* Wlb = Wl + (size_t)b * wstride;
    const float* Xb = X + (size_t)b * xstride;
    float*       Yb = Y + (size_t)b * ystride;

    // ---- B tile: full K=192 x 128 px, fp32 -> bf16 hi/lo, once ----
    #pragma unroll
    for (int i = 0; i < 24; ++i) {                  // 192 rows x 32 float4
        const int c  = tid + 256 * i;
        const int kk = c >> 5;
        const int p4 = (c & 31) * 4;
        const float4 v = *(const float4*)(Xb + (size_t)kk * HW + p0 + p4);
        u64 hp, lp;
        bsplit4(v, hp, lp);
        *(u64*)(sBh + kk * GB_STRIDE + p4) = hp;
        *(u64*)(sBl + kk * GB_STRIDE + p4) = lp;
    }

    for (int mt = 0; mt < nmt; ++mt) {
        const int m0 = mt * 128;
        float acc[4][4][4];
        #pragma unroll
        for (int mi = 0; mi < 4; ++mi)
            #pragma unroll
            for (int ni = 0; ni < 4; ++ni)
                #pragma unroll
                for (int r = 0; r < 4; ++r) acc[mi][ni][r] = 0.f;

        for (int kt = 0; kt < 4; ++kt) {
            const int k0 = kt * 48;
            // A tile: weights rows m0..m0+127, cols k0..k0+47 (L2-resident)
            #pragma unroll
            for (int i = 0; i < 6; ++i) {           // 1536 u64 chunks
                const int c   = tid + 256 * i;
                const int row = c / 12;
                const int cc  = c % 12;
                const int m   = m0 + row;
                u64 vh = 0ull, vl = 0ull;
                if (m < M) {
                    vh = *(const u64*)(Whb + (size_t)m * KDIM + k0 + cc * 4);
                    vl = *(const u64*)(Wlb + (size_t)m * KDIM + k0 + cc * 4);
                }
                *(u64*)(sAh + row * GA_STRIDE + cc * 4) = vh;
                *(u64*)(sAl + row * GA_STRIDE + cc * 4) = vl;
            }
            __syncthreads();

            #pragma unroll
            for (int ks = 0; ks < 3; ++ks) {
                const int kk0 = ks * 16;
                uint32_t bh[4][2], bl[4][2];
                const int brow = k0 + kk0 + (lane & 15);
                #pragma unroll
                for (int ni = 0; ni < 4; ++ni) {
                    const uint32_t boffB =
                        (uint32_t)(brow * GB_STRIDE + wn + ni * 8) * 2;
                    ldm_x2t(bh[ni], uBh + boffB);
                    ldm_x2t(bl[ni], uBl + boffB);
                }
                const int arow = wm + (lane & 15);
                const uint32_t akcol = (uint32_t)(kk0 + ((lane >> 4) << 3));
                #pragma unroll
                for (int mi = 0; mi < 4; ++mi) {
                    uint32_t ah[4], al[4];
                    const uint32_t aoff =
                        (uint32_t)((arow + mi * 16) * GA_STRIDE + akcol) * 2;
                    ldm_x4(ah, uAh + aoff);
                    ldm_x4(al, uAl + aoff);
                    #pragma unroll
                    for (int ni = 0; ni < 4; ++ni) {
                        mma_bf16(acc[mi][ni], ah, bh[ni]);   // Ah*Bh
                        mma_bf16(acc[mi][ni], ah, bl[ni]);   // Ah*Bl
                        mma_bf16(acc[mi][ni], al, bh[ni]);   // Al*Bh
                    }
                }
            }
            __syncthreads();
        }

        const int g  = lane >> 2;
        const int tg = lane & 3;
        #pragma unroll
        for (int mi = 0; mi < 4; ++mi) {
            #pragma unroll
            for (int ni = 0; ni < 4; ++ni) {
                const int m = m0 + wm + mi * 16 + g;
                const int p = p0 + wn + ni * 8 + tg * 2;
                if (m < M)
                    *(float2*)(Yb + (size_t)m * HW + p) =
                        make_float2(acc[mi][ni][0], acc[mi][ni][1]);
                if (m + 8 < M)
                    *(float2*)(Yb + (size_t)(m + 8) * HW + p) =
                        make_float2(acc[mi][ni][2], acc[mi][ni][3]);
            }
        }
    }
}

// ---------------- depthwise 3x3, pad 1, smem-tiled 128x16 ------------------
#define DW_TH 16
__global__ __launch_bounds__(256) void dwconv3x3_t(
    const float* __restrict__ in, const float* __restrict__ wdw,
    float* __restrict__ out)
{
    const int bc = blockIdx.y;                  // 0..BATCH*MQKV-1
    const int h0 = blockIdx.x * DW_TH;
    const int ch = bc % MQKV;
    const float* base = in + (size_t)bc * HW;
    const int tid = threadIdx.x;

    __shared__ __align__(16) float st[DW_TH + 2][132];
    __shared__ float wsh[9];
    if (tid < 9) wsh[tid] = wdw[ch * 9 + tid];

    #pragma unroll
    for (int idx = tid; idx < 18 * 32; idx += 256) {
        const int r  = idx >> 5;
        const int c4 = (idx & 31) << 2;
        const int gh = h0 - 1 + r;
        float4 v = make_float4(0.f, 0.f, 0.f, 0.f);
        if (gh >= 0 && gh < HH) v = *(const float4*)(base + (size_t)gh * WW + c4);
        *(float4*)&st[r][c4] = v;
    }
    __syncthreads();

    const int w     = tid & 127;
    const int strip = tid >> 7;                 // 0 or 1
    const int hb    = strip * 8;                // local pixel rows hb..hb+7
    const bool wl = (w > 0), wr = (w < 127);
    const float w00 = wsh[0], w01 = wsh[1], w02 = wsh[2];
    const float w10 = wsh[3], w11 = wsh[4], w12 = wsh[5];
    const float w20 = wsh[6], w21 = wsh[7], w22 = wsh[8];

    float l0 = wl ? st[hb][w - 1] : 0.f;
    float m0 = st[hb][w];
    float r0 = wr ? st[hb][w + 1] : 0.f;
    float l1 = wl ? st[hb + 1][w - 1] : 0.f;
    float m1 = st[hb + 1][w];
    float r1 = wr ? st[hb + 1][w + 1] : 0.f;

    float* ob = out + (size_t)bc * HW + (size_t)(h0 + hb) * WW + w;
    #pragma unroll
    for (int rr = 0; rr < 8; ++rr) {
        const int sr = hb + rr + 2;
        const float l2 = wl ? st[sr][w - 1] : 0.f;
        const float m2 = st[sr][w];
        const float r2 = wr ? st[sr][w + 1] : 0.f;
        float s = w00 * l0;
        s = fmaf(w01, m0, s); s = fmaf(w02, r0, s);
        s = fmaf(w10, l1, s); s = fmaf(w11, m1, s); s = fmaf(w12, r1, s);
        s = fmaf(w20, l2, s); s = fmaf(w21, m2, s); s = fmaf(w22, r2, s);
        ob[(size_t)rr * WW] = s;
        l0 = l1; m0 = m1; r0 = r1;
        l1 = l2; m1 = m2; r1 = r2;
    }
}

// ---------------- S = q k^T (48x48) on tensor cores + scalar norms ---------
// CTA = (bh, 512-px chunk). smem: 96 rows (q:0-47, k:48-95) x 64 px hi/lo.
// 6 MMA warps tile 3(m16) x 2(n24) over 48x48; warps 6-7 load-only.
#define AP_STRIDE 72
__global__ __launch_bounds__(256) void attn_gram()
{
    __shared__ __align__(16) __nv_bfloat16 sZh[96 * AP_STRIDE];
    __shared__ __align__(16) __nv_bfloat16 sZl[96 * AP_STRIDE];
    const uint32_t uZh = smem_u32(sZh), uZl = smem_u32(sZl);

    const int tid  = threadIdx.x;
    const int lane = tid & 31;
    const int wid  = tid >> 5;
    const int wm   = (wid >> 1) * 16;       // 0,16,32 (warps 0-5)
    const int wn   = (wid & 1) * 24;        // 0,24
    const int bh   = blockIdx.x;
    const int b    = bh >> 2;
    const int hh   = bh & 3;
    const float* qbase = g_dw + ((size_t)b * MQKV + hh * CH) * HW;
    const float* kbase = g_dw + ((size_t)b * MQKV + DIM + hh * CH) * HW;
    const int n0 = blockIdx.y * 512;

    float acc[3][4];
    #pragma unroll
    for (int ni = 0; ni < 3; ++ni)
        #pragma unroll
        for (int r = 0; r < 4; ++r) acc[ni][r] = 0.f;
    float sq[6];
    #pragma unroll
    for (int i = 0; i < 6; ++i) sq[i] = 0.f;

    for (int t = 0; t < 8; ++t) {
        const int nb = n0 + t * 64;
        #pragma unroll
        for (int i = 0; i < 6; ++i) {
            const int c   = tid + 256 * i;
            const int row = c >> 4;
            const int c4  = (c & 15) << 2;
            const float* src = (row < 48)
                ? qbase + (size_t)row * HW + nb + c4
                : kbase + (size_t)(row - 48) * HW + nb + c4;
            const float4 v = *(const float4*)src;
            sq[i] = fmaf(v.x, v.x, sq[i]);
            sq[i] = fmaf(v.y, v.y, sq[i]);
            sq[i] = fmaf(v.z, v.z, sq[i]);
            sq[i] = fmaf(v.w, v.w, sq[i]);
            u64 hp, lp;
            bsplit4(v, hp, lp);
            *(u64*)(sZh + row * AP_STRIDE + c4) = hp;
            *(u64*)(sZl + row * AP_STRIDE + c4) = lp;
        }
        __syncthreads();

        if (wid < 6) {
            #pragma unroll
            for (int ks = 0; ks < 4; ++ks) {
                const int kk0 = ks * 16;
                const int arow = wm + (lane & 15);
                const uint32_t akcol = (uint32_t)(kk0 + ((lane >> 4) << 3));
                uint32_t ah[4], al[4];
                const uint32_t aoff =
                    (uint32_t)(arow * AP_STRIDE + akcol) * 2;
                ldm_x4(ah, uZh + aoff);
                ldm_x4(al, uZl + aoff);
                const int l16 = lane & 15;
                const int bn  = l16 & 7;
                const int bk  = kk0 + ((l16 >> 3) << 3);
                #pragma unroll
                for (int ni = 0; ni < 3; ++ni) {
                    uint32_t bfh[2], bfl[2];
                    const uint32_t boff =
                        (uint32_t)((48 + wn + ni * 8 + bn) * AP_STRIDE + bk) * 2;
                    ldm_x2(bfh, uZh + boff);
                    ldm_x2(bfl, uZl + boff);
                    mma_bf16(acc[ni], ah, bfh);
                    mma_bf16(acc[ni], ah, bfl);
                    mma_bf16(acc[ni], al, bfh);
                }
            }
        }
        __syncthreads();
    }

    #pragma unroll
    for (int i = 0; i < 6; ++i) {
        float s = sq[i];
        s += __shfl_xor_sync(0xffffffffu, s, 1);
        s += __shfl_xor_sync(0xffffffffu, s, 2);
        s += __shfl_xor_sync(0xffffffffu, s, 4);
        s += __shfl_xor_sync(0xffffffffu, s, 8);
        if ((lane & 15) == 0) {
            const int row = (tid >> 4) + 16 * i;
            atomicAdd(&g_norm[bh * 96 + row], s);
        }
    }

    if (wid < 6) {
        float* Sp = g_S + (size_t)bh * CH * CH;
        const int g  = lane >> 2;
        const int tg = lane & 3;
        #pragma unroll
        for (int ni = 0; ni < 3; ++ni) {
            const int m = wm + g;
            const int n = wn + ni * 8 + tg * 2;
            atomicAdd(&Sp[m * CH + n],           acc[ni][0]);
            atomicAdd(&Sp[m * CH + n + 1],       acc[ni][1]);
            atomicAdd(&Sp[(m + 8) * CH + n],     acc[ni][2]);
            atomicAdd(&Sp[(m + 8) * CH + n + 1], acc[ni][3]);
        }
    }
}

// ---------------- finalize: normalize, per-row topk/softmax, combine -------
// k values: int(48*rate) in IEEE double: {24, 32 (round-to-even), 36, 38}
__global__ void finalize_comb(const float* __restrict__ temperature,
                              const float* __restrict__ attn_w)
{
    const int bh = blockIdx.x;
    const int hh = bh & 3;
    const int i  = threadIdx.x;
    if (i >= CH) return;

    float a[CH];
    const float nq = fmaxf(sqrtf(g_norm[bh * 96 + i]), 1e-12f);
    const float tmp = temperature[hh];
    for (int j = 0; j < CH; ++j) {
        const float nk = fmaxf(sqrtf(g_norm[bh * 96 + 48 + j]), 1e-12f);
        a[j] = g_S[bh * CH * CH + i * CH + j] * tmp / (nq * nk);
    }

    int rank[CH];
    for (int j = 0; j < CH; ++j) {
        int r = 0;
        for (int l = 0; l < CH; ++l)
            if (a[l] > a[j] || (a[l] == a[j] && l < j)) r++;
        rank[j] = r;
    }

    float comb[CH];
    for (int j = 0; j < CH; ++j) comb[j] = 0.f;

    const int kvals[4] = {24, 32, 36, 38};
    for (int r = 0; r < 4; ++r) {
        const int kv = kvals[r];
        float m = -INFINITY;
        for (int j = 0; j < CH; ++j)
            if (rank[j] < kv) m = fmaxf(m, a[j]);
        float e[CH];
        float ssum = 0.f;
        for (int j = 0; j < CH; ++j) {
            e[j] = (rank[j] < kv) ? expf(a[j] - m) : 0.f;
            ssum += e[j];
        }
        const float wgt = attn_w[r] / ssum;
        for (int j = 0; j < CH; ++j) comb[j] = fmaf(e[j], wgt, comb[j]);
    }

    for (int j = 0; j < CH; ++j)
        g_comb[bh * CH * CH + i * CH + j] = comb[j];
}

// ---------------- W_eff = W_proj . blockdiag(comb), split to bf16 hi/lo ----
__global__ __launch_bounds__(192) void weff_compute(const float* __restrict__ wproj)
{
    const int bh = blockIdx.x;          // 0..15
    const int b  = bh >> 2;
    const int hh = bh & 3;
    const int o  = threadIdx.x;         // 0..191

    __shared__ float cs[CH][CH];
    for (int l = o; l < CH * CH; l += 192)
        cs[l / CH][l % CH] = g_comb[bh * CH * CH + l];
    __syncthreads();

    float wr[CH];
    #pragma unroll
    for (int c = 0; c < CH; ++c) wr[c] = wproj[o * KDIM + hh * CH + c];

    __nv_bfloat16* eh = g_weh + ((size_t)b * DIM + o) * KDIM + hh * CH;
    __nv_bfloat16* el = g_wel + ((size_t)b * DIM + o) * KDIM + hh * CH;
    for (int d = 0; d < CH; ++d) {
        float s = 0.f;
        #pragma unroll
        for (int c = 0; c < CH; ++c) s = fmaf(wr[c], cs[c][d], s);
        const __nv_bfloat16 h = __float2bfloat16(s);
        eh[d] = h;
        el[d] = __float2bfloat16(s - __bfloat162float(h));
    }
}

// ---------------- launch ----------------------------------------------------
extern "C" void kernel_launch(void* const* d_in, const int* in_sizes, int n_in,
                              void* d_out, int out_size)
{
    const float* x           = (const float*)d_in[0];  // [4,192,128,128]
    const float* w_qkv       = (const float*)d_in[1];  // [576,192]
    const float* w_dw        = (const float*)d_in[2];  // [576,9]
    const float* w_proj      = (const float*)d_in[3];  // [192,192]
    const float* temperature = (const float*)d_in[4];  // [4]
    const float* attn_w      = (const float*)d_in[5];  // [4]
    float* out = (float*)d_out;

    float* qkv; cudaGetSymbolAddress((void**)&qkv, g_qkv);
    float* dw;  cudaGetSymbolAddress((void**)&dw,  g_dw);
    __nv_bfloat16* wqh; cudaGetSymbolAddress((void**)&wqh, g_wqh);
    __nv_bfloat16* wql; cudaGetSymbolAddress((void**)&wql, g_wql);
    __nv_bfloat16* weh; cudaGetSymbolAddress((void**)&weh, g_weh);
    __nv_bfloat16* wel; cudaGetSymbolAddress((void**)&wel, g_wel);

    static bool attr_set = false;
    if (!attr_set) {
        cudaFuncSetAttribute(gemm_mma,
                             cudaFuncAttributeMaxDynamicSharedMemorySize,
                             G_SMEM_BYTES);
        attr_set = true;
    }

    // 0. split qkv weights into bf16 hi/lo + zero S/norm accumulators
    w_split<<<(MQKV * KDIM + 255) / 256, 256>>>(w_qkv);

    // 1. qkv = w_qkv @ x  (tensor cores; full-K B tile, m-tile loop)
    gemm_mma<<<dim3(HW / 128, 1, BATCH), 256, G_SMEM_BYTES>>>(
        wqh, wql, x, qkv, MQKV, 5, 0, (long)KDIM * HW, (long)MQKV * HW);

    // 2. depthwise 3x3 (smem-tiled, all 576 channels)
    dwconv3x3_t<<<dim3(HH / DW_TH, BATCH * MQKV), 256>>>(qkv, w_dw, dw);

    // 3. S = q.k^T (tensor cores, 48x48 only) + norms (scalar, fused)
    attn_gram<<<dim3(BHN, 32), 256>>>();

    // 4. combined attention weights (topk + softmax + weighted sum)
    finalize_comb<<<BHN, 64>>>(temperature, attn_w);

    // 5. W_eff[b] = W_proj . blockdiag(comb_b)  (fuses attn_apply into proj)
    weff_compute<<<BHN, 192>>>(w_proj);

    // 6. out = W_eff[b] @ v  (tensor cores, per-batch weights)
    gemm_mma<<<dim3(HW / 128, 1, BATCH), 256, G_SMEM_BYTES>>>(
        weh, wel, dw + (size_t)2 * DIM * HW, out, DIM, 2,
        (long)DIM * KDIM, (long)MQKV * HW, (long)DIM * HW);
}

// round 14
// speedup vs baseline: 1.2283x; 1.0410x over previous
#include <cuda_runtime.h>
#include <cuda_bf16.h>
#include <math.h>
#include <stdint.h>

// Problem constants
#define BATCH  4
#define DIM    192
#define HH     128
#define WW     128
#define HW     16384            // 128*128
#define HEADS  4
#define CH     48               // DIM / HEADS
#define MQKV   576              // 3*DIM
#define KDIM   192              // reduction dim of 1x1 convs
#define BHN    16               // BATCH*HEADS

typedef unsigned long long u64;

// ---------------- warp-MMA helpers (baseline ISA, no arch suffix) ----------
__device__ __forceinline__ uint32_t smem_u32(const void* p) {
    uint32_t a;
    asm("{ .reg .u64 t; cvta.to.shared.u64 t, %1; cvt.u32.u64 %0, t; }"
        : "=r"(a) : "l"(p));
    return a;
}
__device__ __forceinline__ void ldm_x4(uint32_t r[4], uint32_t addr) {
    asm volatile("ldmatrix.sync.aligned.m8n8.x4.shared.b16 {%0,%1,%2,%3}, [%4];"
                 : "=r"(r[0]), "=r"(r[1]), "=r"(r[2]), "=r"(r[3]) : "r"(addr));
}
__device__ __forceinline__ void ldm_x2(uint32_t r[2], uint32_t addr) {
    asm volatile("ldmatrix.sync.aligned.m8n8.x2.shared.b16 {%0,%1}, [%2];"
                 : "=r"(r[0]), "=r"(r[1]) : "r"(addr));
}
__device__ __forceinline__ void ldm_x2t(uint32_t r[2], uint32_t addr) {
    asm volatile("ldmatrix.sync.aligned.m8n8.x2.trans.shared.b16 {%0,%1}, [%2];"
                 : "=r"(r[0]), "=r"(r[1]) : "r"(addr));
}
__device__ __forceinline__ void mma_bf16(float c[4], const uint32_t a[4],
                                         const uint32_t b[2]) {
    asm volatile(
        "mma.sync.aligned.m16n8k16.row.col.f32.bf16.bf16.f32 "
        "{%0,%1,%2,%3}, {%4,%5,%6,%7}, {%8,%9}, {%0,%1,%2,%3};"
        : "+f"(c[0]), "+f"(c[1]), "+f"(c[2]), "+f"(c[3])
        : "r"(a[0]), "r"(a[1]), "r"(a[2]), "r"(a[3]), "r"(b[0]), "r"(b[1]));
}
__device__ __forceinline__ void bsplit4(const float4 v, u64& hp, u64& lp) {
    __nv_bfloat16 h[4], l[4];
    h[0] = __float2bfloat16(v.x); l[0] = __float2bfloat16(v.x - __bfloat162float(h[0]));
    h[1] = __float2bfloat16(v.y); l[1] = __float2bfloat16(v.y - __bfloat162float(h[1]));
    h[2] = __float2bfloat16(v.z); l[2] = __float2bfloat16(v.z - __bfloat162float(h[2]));
    h[3] = __float2bfloat16(v.w); l[3] = __float2bfloat16(v.w - __bfloat162float(h[3]));
    hp = *(const u64*)h;
    lp = *(const u64*)l;
}

// ---------------- scratch (device globals; no allocation allowed) ----------
__device__ __align__(16) float g_qkv[(size_t)BATCH * MQKV * HW];  // conv1x1 qkv output
__device__ __align__(16) float g_dw [(size_t)BATCH * MQKV * HW];  // after depthwise 3x3
__device__ __align__(16) float g_S   [BHN * CH * CH];             // q.k^T partial sums
__device__ __align__(16) float g_norm[BHN * 96];                  // sumsq: q rows then k rows
__device__ __align__(16) float g_comb[BHN * CH * CH];             // combined attention weights
// bf16 hi/lo split weights
__device__ __align__(16) __nv_bfloat16 g_wqh[MQKV * KDIM];
__device__ __align__(16) __nv_bfloat16 g_wql[MQKV * KDIM];
__device__ __align__(16) __nv_bfloat16 g_weh[BATCH * DIM * KDIM]; // W_eff hi (per batch)
__device__ __align__(16) __nv_bfloat16 g_wel[BATCH * DIM * KDIM]; // W_eff lo

// ---------------- weight split + zero accumulators (one launch) ------------
__global__ void w_split(const float* __restrict__ wq)
{
    const int i = blockIdx.x * 256 + threadIdx.x;
    if (i < MQKV * KDIM) {
        const float x = wq[i];
        const __nv_bfloat16 h = __float2bfloat16(x);
        g_wqh[i] = h;
        g_wql[i] = __float2bfloat16(x - __bfloat162float(h));
    }
    if (i < BHN * CH * CH) g_S[i] = 0.f;
    if (i < BHN * 96)      g_norm[i] = 0.f;
}

// ---------------- tensor-core conv1x1 via mma.sync bf16 3-product split ----
// Y[b][m][p] = sum_k W_b[m][k] X_b[k][p].
// CTA owns a 64-pixel block; loads/converts the FULL-K B tile (192x64,
// hi/lo) ONCE, then loops over all m-tiles, staging A per (mt, kt).
// 8 warps (2m x 4n), warp tile 64x16.  smem 84KB -> 2 CTAs/SM.
#define GA_STRIDE 56
#define GB_STRIDE 72
#define SM_BH 0
#define SM_BL (192 * GB_STRIDE)                     // 13824 (bf16 idx)
#define SM_AH (2 * 192 * GB_STRIDE)                 // 27648
#define SM_AL (2 * 192 * GB_STRIDE + 128 * GA_STRIDE)
#define G_SMEM_BF16 (2 * 192 * GB_STRIDE + 2 * 128 * GA_STRIDE)
#define G_SMEM_BYTES (G_SMEM_BF16 * 2)              // 83968

__global__ __launch_bounds__(256, 2) void gemm_mma(
    const __nv_bfloat16* __restrict__ Wh, const __nv_bfloat16* __restrict__ Wl,
    const float* __restrict__ X, float* __restrict__ Y, int M, int nmt,
    long wstride, long xstride, long ystride)
{
    extern __shared__ __align__(16) __nv_bfloat16 sm[];
    __nv_bfloat16* sBh = sm + SM_BH;
    __nv_bfloat16* sBl = sm + SM_BL;
    __nv_bfloat16* sAh = sm + SM_AH;
    __nv_bfloat16* sAl = sm + SM_AL;
    const uint32_t uBh = smem_u32(sBh), uBl = smem_u32(sBl);
    const uint32_t uAh = smem_u32(sAh), uAl = smem_u32(sAl);

    const int tid  = threadIdx.x;
    const int lane = tid & 31;
    const int wid  = tid >> 5;
    const int wm   = (wid >> 2) * 64;     // warp m offset (2 groups)
    const int wn   = (wid & 3) * 16;      // warp n offset (4 groups of 16)
    const int b    = blockIdx.z;
    const int p0   = blockIdx.x * 64;
    const __nv_bfloat16* Whb = Wh + (size_t)b * wstride;
    const __nv_bfloat16* Wlb = Wl + (size_t)b * wstride;
    const float* Xb = X + (size_t)b * xstride;
    float*       Yb = Y + (size_t)b * ystride;

    // ---- B tile: full K=192 x 64 px, fp32 -> bf16 hi/lo, once ----
    #pragma unroll
    for (int i = 0; i < 12; ++i) {                  // 192 rows x 16 float4
        const int c  = tid + 256 * i;
        const int kk = c >> 4;
        const int p4 = (c & 15) * 4;
        const float4 v = *(const float4*)(Xb + (size_t)kk * HW + p0 + p4);
        u64 hp, lp;
        bsplit4(v, hp, lp);
        *(u64*)(sBh + kk * GB_STRIDE + p4) = hp;
        *(u64*)(sBl + kk * GB_STRIDE + p4) = lp;
    }

    for (int mt = 0; mt < nmt; ++mt) {
        const int m0 = mt * 128;
        float acc[4][2][4];
        #pragma unroll
        for (int mi = 0; mi < 4; ++mi)
            #pragma unroll
            for (int ni = 0; ni < 2; ++ni)
                #pragma unroll
                for (int r = 0; r < 4; ++r) acc[mi][ni][r] = 0.f;

        for (int kt = 0; kt < 4; ++kt) {
            const int k0 = kt * 48;
            // A tile: weights rows m0..m0+127, cols k0..k0+47 (L2-resident)
            #pragma unroll
            for (int i = 0; i < 6; ++i) {           // 1536 u64 chunks
                const int c   = tid + 256 * i;
                const int row = c / 12;
                const int cc  = c % 12;
                const int m   = m0 + row;
                u64 vh = 0ull, vl = 0ull;
                if (m < M) {
                    vh = *(const u64*)(Whb + (size_t)m * KDIM + k0 + cc * 4);
                    vl = *(const u64*)(Wlb + (size_t)m * KDIM + k0 + cc * 4);
                }
                *(u64*)(sAh + row * GA_STRIDE + cc * 4) = vh;
                *(u64*)(sAl + row * GA_STRIDE + cc * 4) = vl;
            }
            __syncthreads();

            #pragma unroll
            for (int ks = 0; ks < 3; ++ks) {
                const int kk0 = ks * 16;
                uint32_t bh[2][2], bl[2][2];
                const int brow = k0 + kk0 + (lane & 15);
                #pragma unroll
                for (int ni = 0; ni < 2; ++ni) {
                    const uint32_t boffB =
                        (uint32_t)(brow * GB_STRIDE + wn + ni * 8) * 2;
                    ldm_x2t(bh[ni], uBh + boffB);
                    ldm_x2t(bl[ni], uBl + boffB);
                }
                const int arow = wm + (lane & 15);
                const uint32_t akcol = (uint32_t)(kk0 + ((lane >> 4) << 3));
                #pragma unroll
                for (int mi = 0; mi < 4; ++mi) {
                    uint32_t ah[4], al[4];
                    const uint32_t aoff =
                        (uint32_t)((arow + mi * 16) * GA_STRIDE + akcol) * 2;
                    ldm_x4(ah, uAh + aoff);
                    ldm_x4(al, uAl + aoff);
                    #pragma unroll
                    for (int ni = 0; ni < 2; ++ni) {
                        mma_bf16(acc[mi][ni], ah, bh[ni]);   // Ah*Bh
                        mma_bf16(acc[mi][ni], ah, bl[ni]);   // Ah*Bl
                        mma_bf16(acc[mi][ni], al, bh[ni]);   // Al*Bh
                    }
                }
            }
            __syncthreads();
        }

        const int g  = lane >> 2;
        const int tg = lane & 3;
        #pragma unroll
        for (int mi = 0; mi < 4; ++mi) {
            #pragma unroll
            for (int ni = 0; ni < 2; ++ni) {
                const int m = m0 + wm + mi * 16 + g;
                const int p = p0 + wn + ni * 8 + tg * 2;
                if (m < M)
                    *(float2*)(Yb + (size_t)m * HW + p) =
                        make_float2(acc[mi][ni][0], acc[mi][ni][1]);
                if (m + 8 < M)
                    *(float2*)(Yb + (size_t)(m + 8) * HW + p) =
                        make_float2(acc[mi][ni][2], acc[mi][ni][3]);
            }
        }
    }
}

// ---------------- depthwise 3x3, pad 1, smem-tiled 128x16 ------------------
#define DW_TH 16
__global__ __launch_bounds__(256) void dwconv3x3_t(
    const float* __restrict__ in, const float* __restrict__ wdw,
    float* __restrict__ out)
{
    const int bc = blockIdx.y;                  // 0..BATCH*MQKV-1
    const int h0 = blockIdx.x * DW_TH;
    const int ch = bc % MQKV;
    const float* base = in + (size_t)bc * HW;
    const int tid = threadIdx.x;

    __shared__ __align__(16) float st[DW_TH + 2][132];
    __shared__ float wsh[9];
    if (tid < 9) wsh[tid] = wdw[ch * 9 + tid];

    #pragma unroll
    for (int idx = tid; idx < 18 * 32; idx += 256) {
        const int r  = idx >> 5;
        const int c4 = (idx & 31) << 2;
        const int gh = h0 - 1 + r;
        float4 v = make_float4(0.f, 0.f, 0.f, 0.f);
        if (gh >= 0 && gh < HH) v = *(const float4*)(base + (size_t)gh * WW + c4);
        *(float4*)&st[r][c4] = v;
    }
    __syncthreads();

    const int w     = tid & 127;
    const int strip = tid >> 7;                 // 0 or 1
    const int hb    = strip * 8;                // local pixel rows hb..hb+7
    const bool wl = (w > 0), wr = (w < 127);
    const float w00 = wsh[0], w01 = wsh[1], w02 = wsh[2];
    const float w10 = wsh[3], w11 = wsh[4], w12 = wsh[5];
    const float w20 = wsh[6], w21 = wsh[7], w22 = wsh[8];

    float l0 = wl ? st[hb][w - 1] : 0.f;
    float m0 = st[hb][w];
    float r0 = wr ? st[hb][w + 1] : 0.f;
    float l1 = wl ? st[hb + 1][w - 1] : 0.f;
    float m1 = st[hb + 1][w];
    float r1 = wr ? st[hb + 1][w + 1] : 0.f;

    float* ob = out + (size_t)bc * HW + (size_t)(h0 + hb) * WW + w;
    #pragma unroll
    for (int rr = 0; rr < 8; ++rr) {
        const int sr = hb + rr + 2;
        const float l2 = wl ? st[sr][w - 1] : 0.f;
        const float m2 = st[sr][w];
        const float r2 = wr ? st[sr][w + 1] : 0.f;
        float s = w00 * l0;
        s = fmaf(w01, m0, s); s = fmaf(w02, r0, s);
        s = fmaf(w10, l1, s); s = fmaf(w11, m1, s); s = fmaf(w12, r1, s);
        s = fmaf(w20, l2, s); s = fmaf(w21, m2, s); s = fmaf(w22, r2, s);
        ob[(size_t)rr * WW] = s;
        l0 = l1; m0 = m1; r0 = r1;
        l1 = l2; m1 = m2; r1 = r2;
    }
}

// ---------------- S = q k^T (48x48) on tensor cores + scalar norms ---------
#define AP_STRIDE 72
__global__ __launch_bounds__(256) void attn_gram()
{
    __shared__ __align__(16) __nv_bfloat16 sZh[96 * AP_STRIDE];
    __shared__ __align__(16) __nv_bfloat16 sZl[96 * AP_STRIDE];
    const uint32_t uZh = smem_u32(sZh), uZl = smem_u32(sZl);

    const int tid  = threadIdx.x;
    const int lane = tid & 31;
    const int wid  = tid >> 5;
    const int wm   = (wid >> 1) * 16;       // 0,16,32 (warps 0-5)
    const int wn   = (wid & 1) * 24;        // 0,24
    const int bh   = blockIdx.x;
    const int b    = bh >> 2;
    const int hh   = bh & 3;
    const float* qbase = g_dw + ((size_t)b * MQKV + hh * CH) * HW;
    const float* kbase = g_dw + ((size_t)b * MQKV + DIM + hh * CH) * HW;
    const int n0 = blockIdx.y * 512;

    float acc[3][4];
    #pragma unroll
    for (int ni = 0; ni < 3; ++ni)
        #pragma unroll
        for (int r = 0; r < 4; ++r) acc[ni][r] = 0.f;
    float sq[6];
    #pragma unroll
    for (int i = 0; i < 6; ++i) sq[i] = 0.f;

    for (int t = 0; t < 8; ++t) {
        const int nb = n0 + t * 64;
        #pragma unroll
        for (int i = 0; i < 6; ++i) {
            const int c   = tid + 256 * i;
            const int row = c >> 4;
            const int c4  = (c & 15) << 2;
            const float* src = (row < 48)
                ? qbase + (size_t)row * HW + nb + c4
                : kbase + (size_t)(row - 48) * HW + nb + c4;
            const float4 v = *(const float4*)src;
            sq[i] = fmaf(v.x, v.x, sq[i]);
            sq[i] = fmaf(v.y, v.y, sq[i]);
            sq[i] = fmaf(v.z, v.z, sq[i]);
            sq[i] = fmaf(v.w, v.w, sq[i]);
            u64 hp, lp;
            bsplit4(v, hp, lp);
            *(u64*)(sZh + row * AP_STRIDE + c4) = hp;
            *(u64*)(sZl + row * AP_STRIDE + c4) = lp;
        }
        __syncthreads();

        if (wid < 6) {
            #pragma unroll
            for (int ks = 0; ks < 4; ++ks) {
                const int kk0 = ks * 16;
                const int arow = wm + (lane & 15);
                const uint32_t akcol = (uint32_t)(kk0 + ((lane >> 4) << 3));
                uint32_t ah[4], al[4];
                const uint32_t aoff =
                    (uint32_t)(arow * AP_STRIDE + akcol) * 2;
                ldm_x4(ah, uZh + aoff);
                ldm_x4(al, uZl + aoff);
                const int l16 = lane & 15;
                const int bn  = l16 & 7;
                const int bk  = kk0 + ((l16 >> 3) << 3);
                #pragma unroll
                for (int ni = 0; ni < 3; ++ni) {
                    uint32_t bfh[2], bfl[2];
                    const uint32_t boff =
                        (uint32_t)((48 + wn + ni * 8 + bn) * AP_STRIDE + bk) * 2;
                    ldm_x2(bfh, uZh + boff);
                    ldm_x2(bfl, uZl + boff);
                    mma_bf16(acc[ni], ah, bfh);
                    mma_bf16(acc[ni], ah, bfl);
                    mma_bf16(acc[ni], al, bfh);
                }
            }
        }
        __syncthreads();
    }

    #pragma unroll
    for (int i = 0; i < 6; ++i) {
        float s = sq[i];
        s += __shfl_xor_sync(0xffffffffu, s, 1);
        s += __shfl_xor_sync(0xffffffffu, s, 2);
        s += __shfl_xor_sync(0xffffffffu, s, 4);
        s += __shfl_xor_sync(0xffffffffu, s, 8);
        if ((lane & 15) == 0) {
            const int row = (tid >> 4) + 16 * i;
            atomicAdd(&g_norm[bh * 96 + row], s);
        }
    }

    if (wid < 6) {
        float* Sp = g_S + (size_t)bh * CH * CH;
        const int g  = lane >> 2;
        const int tg = lane & 3;
        #pragma unroll
        for (int ni = 0; ni < 3; ++ni) {
            const int m = wm + g;
            const int n = wn + ni * 8 + tg * 2;
            atomicAdd(&Sp[m * CH + n],           acc[ni][0]);
            atomicAdd(&Sp[m * CH + n + 1],       acc[ni][1]);
            atomicAdd(&Sp[(m + 8) * CH + n],     acc[ni][2]);
            atomicAdd(&Sp[(m + 8) * CH + n + 1], acc[ni][3]);
        }
    }
}

// ---------------- finalize: normalize, per-row topk/softmax, combine -------
// k values: int(48*rate) in IEEE double: {24, 32 (round-to-even), 36, 38}
__global__ void finalize_comb(const float* __restrict__ temperature,
                              const float* __restrict__ attn_w)
{
    const int bh = blockIdx.x;
    const int hh = bh & 3;
    const int i  = threadIdx.x;
    if (i >= CH) return;

    float a[CH];
    const float nq = fmaxf(sqrtf(g_norm[bh * 96 + i]), 1e-12f);
    const float tmp = temperature[hh];
    for (int j = 0; j < CH; ++j) {
        const float nk = fmaxf(sqrtf(g_norm[bh * 96 + 48 + j]), 1e-12f);
        a[j] = g_S[bh * CH * CH + i * CH + j] * tmp / (nq * nk);
    }

    int rank[CH];
    for (int j = 0; j < CH; ++j) {
        int r = 0;
        for (int l = 0; l < CH; ++l)
            if (a[l] > a[j] || (a[l] == a[j] && l < j)) r++;
        rank[j] = r;
    }

    float comb[CH];
    for (int j = 0; j < CH; ++j) comb[j] = 0.f;

    const int kvals[4] = {24, 32, 36, 38};
    for (int r = 0; r < 4; ++r) {
        const int kv = kvals[r];
        float m = -INFINITY;
        for (int j = 0; j < CH; ++j)
            if (rank[j] < kv) m = fmaxf(m, a[j]);
        float e[CH];
        float ssum = 0.f;
        for (int j = 0; j < CH; ++j) {
            e[j] = (rank[j] < kv) ? expf(a[j] - m) : 0.f;
            ssum += e[j];
        }
        const float wgt = attn_w[r] / ssum;
        for (int j = 0; j < CH; ++j) comb[j] = fmaf(e[j], wgt, comb[j]);
    }

    for (int j = 0; j < CH; ++j)
        g_comb[bh * CH * CH + i * CH + j] = comb[j];
}

// ---------------- W_eff = W_proj . blockdiag(comb), split to bf16 hi/lo ----
__global__ __launch_bounds__(192) void weff_compute(const float* __restrict__ wproj)
{
    const int bh = blockIdx.x;          // 0..15
    const int b  = bh >> 2;
    const int hh = bh & 3;
    const int o  = threadIdx.x;         // 0..191

    __shared__ float cs[CH][CH];
    for (int l = o; l < CH * CH; l += 192)
        cs[l / CH][l % CH] = g_comb[bh * CH * CH + l];
    __syncthreads();

    float wr[CH];
    #pragma unroll
    for (int c = 0; c < CH; ++c) wr[c] = wproj[o * KDIM + hh * CH + c];

    __nv_bfloat16* eh = g_weh + ((size_t)b * DIM + o) * KDIM + hh * CH;
    __nv_bfloat16* el = g_wel + ((size_t)b * DIM + o) * KDIM + hh * CH;
    for (int d = 0; d < CH; ++d) {
        float s = 0.f;
        #pragma unroll
        for (int c = 0; c < CH; ++c) s = fmaf(wr[c], cs[c][d], s);
        const __nv_bfloat16 h = __float2bfloat16(s);
        eh[d] = h;
        el[d] = __float2bfloat16(s - __bfloat162float(h));
    }
}

// ---------------- launch ----------------------------------------------------
extern "C" void kernel_launch(void* const* d_in, const int* in_sizes, int n_in,
                              void* d_out, int out_size)
{
    const float* x           = (const float*)d_in[0];  // [4,192,128,128]
    const float* w_qkv       = (const float*)d_in[1];  // [576,192]
    const float* w_dw        = (const float*)d_in[2];  // [576,9]
    const float* w_proj      = (const float*)d_in[3];  // [192,192]
    const float* temperature = (const float*)d_in[4];  // [4]
    const float* attn_w      = (const float*)d_in[5];  // [4]
    float* out = (float*)d_out;

    float* qkv; cudaGetSymbolAddress((void**)&qkv, g_qkv);
    float* dw;  cudaGetSymbolAddress((void**)&dw,  g_dw);
    __nv_bfloat16* wqh; cudaGetSymbolAddress((void**)&wqh, g_wqh);
    __nv_bfloat16* wql; cudaGetSymbolAddress((void**)&wql, g_wql);
    __nv_bfloat16* weh; cudaGetSymbolAddress((void**)&weh, g_weh);
    __nv_bfloat16* wel; cudaGetSymbolAddress((void**)&wel, g_wel);

    static bool attr_set = false;
    if (!attr_set) {
        cudaFuncSetAttribute(gemm_mma,
                             cudaFuncAttributeMaxDynamicSharedMemorySize,
                             G_SMEM_BYTES);
        attr_set = true;
    }

    // 0. split qkv weights into bf16 hi/lo + zero S/norm accumulators
    w_split<<<(MQKV * KDIM + 255) / 256, 256>>>(w_qkv);

    // 1. qkv = w_qkv @ x  (tensor cores; full-K B tile, m-tile loop, 2 CTA/SM)
    gemm_mma<<<dim3(HW / 64, 1, BATCH), 256, G_SMEM_BYTES>>>(
        wqh, wql, x, qkv, MQKV, 5, 0, (long)KDIM * HW, (long)MQKV * HW);

    // 2. depthwise 3x3 (smem-tiled, all 576 channels)
    dwconv3x3_t<<<dim3(HH / DW_TH, BATCH * MQKV), 256>>>(qkv, w_dw, dw);

    // 3. S = q.k^T (tensor cores, 48x48 only) + norms (scalar, fused)
    attn_gram<<<dim3(BHN, 32), 256>>>();

    // 4. combined attention weights (topk + softmax + weighted sum)
    finalize_comb<<<BHN, 64>>>(temperature, attn_w);

    // 5. W_eff[b] = W_proj . blockdiag(comb_b)  (fuses attn_apply into proj)
    weff_compute<<<BHN, 192>>>(w_proj);

    // 6. out = W_eff[b] @ v  (tensor cores, per-batch weights)
    gemm_mma<<<dim3(HW / 64, 1, BATCH), 256, G_SMEM_BYTES>>>(
        weh, wel, dw + (size_t)2 * DIM * HW, out, DIM, 2,
        (long)DIM * KDIM, (long)MQKV * HW, (long)DIM * HW);
}

// round 16
// speedup vs baseline: 1.3138x; 1.0696x over previous
#include <cuda_runtime.h>
#include <cuda_bf16.h>
#include <math.h>
#include <stdint.h>

// Problem constants
#define BATCH  4
#define DIM    192
#define HH     128
#define WW     128
#define HW     16384            // 128*128
#define HEADS  4
#define CH     48               // DIM / HEADS
#define MQKV   576              // 3*DIM
#define KDIM   192              // reduction dim of 1x1 convs
#define BHN    16               // BATCH*HEADS

typedef unsigned long long u64;

// ---------------- warp-MMA helpers (baseline ISA, no arch suffix) ----------
__device__ __forceinline__ uint32_t smem_u32(const void* p) {
    uint32_t a;
    asm("{ .reg .u64 t; cvta.to.shared.u64 t, %1; cvt.u32.u64 %0, t; }"
        : "=r"(a) : "l"(p));
    return a;
}
__device__ __forceinline__ void ldm_x4(uint32_t r[4], uint32_t addr) {
    asm volatile("ldmatrix.sync.aligned.m8n8.x4.shared.b16 {%0,%1,%2,%3}, [%4];"
                 : "=r"(r[0]), "=r"(r[1]), "=r"(r[2]), "=r"(r[3]) : "r"(addr));
}
__device__ __forceinline__ void ldm_x2(uint32_t r[2], uint32_t addr) {
    asm volatile("ldmatrix.sync.aligned.m8n8.x2.shared.b16 {%0,%1}, [%2];"
                 : "=r"(r[0]), "=r"(r[1]) : "r"(addr));
}
__device__ __forceinline__ void ldm_x2t(uint32_t r[2], uint32_t addr) {
    asm volatile("ldmatrix.sync.aligned.m8n8.x2.trans.shared.b16 {%0,%1}, [%2];"
                 : "=r"(r[0]), "=r"(r[1]) : "r"(addr));
}
__device__ __forceinline__ void mma_bf16(float c[4], const uint32_t a[4],
                                         const uint32_t b[2]) {
    asm volatile(
        "mma.sync.aligned.m16n8k16.row.col.f32.bf16.bf16.f32 "
        "{%0,%1,%2,%3}, {%4,%5,%6,%7}, {%8,%9}, {%0,%1,%2,%3};"
        : "+f"(c[0]), "+f"(c[1]), "+f"(c[2]), "+f"(c[3])
        : "r"(a[0]), "r"(a[1]), "r"(a[2]), "r"(a[3]), "r"(b[0]), "r"(b[1]));
}
__device__ __forceinline__ void bsplit4(const float4 v, u64& hp, u64& lp) {
    __nv_bfloat16 h[4], l[4];
    h[0] = __float2bfloat16(v.x); l[0] = __float2bfloat16(v.x - __bfloat162float(h[0]));
    h[1] = __float2bfloat16(v.y); l[1] = __float2bfloat16(v.y - __bfloat162float(h[1]));
    h[2] = __float2bfloat16(v.z); l[2] = __float2bfloat16(v.z - __bfloat162float(h[2]));
    h[3] = __float2bfloat16(v.w); l[3] = __float2bfloat16(v.w - __bfloat162float(h[3]));
    hp = *(const u64*)h;
    lp = *(const u64*)l;
}
// fragment-layout index for A element (local row lr 0-15, local col lc 0-15)
// within one 16x16 block: [lane][8 bf16]; lane=(lr&7)*4+(lc&7)/2,
// reg=(lr>>3)|((lc>>3)<<1), half=lc&1.  (mma.m16n8k16 A layout.)
__device__ __forceinline__ int frag_idx(int lr, int lc) {
    const int lane = ((lr & 7) << 2) | ((lc & 7) >> 1);
    const int reg  = (lr >> 3) | ((lc >> 3) << 1);
    return lane * 8 + reg * 2 + (lc & 1);
}

// ---------------- scratch (device globals; no allocation allowed) ----------
__device__ __align__(16) float g_qkv[(size_t)BATCH * MQKV * HW];  // conv1x1 qkv output
__device__ __align__(16) float g_dw [(size_t)BATCH * MQKV * HW];  // after depthwise 3x3
__device__ __align__(16) float g_S   [BHN * CH * CH];             // q.k^T partial sums
__device__ __align__(16) float g_norm[BHN * 96];                  // sumsq: q rows then k rows
__device__ __align__(16) float g_comb[BHN * CH * CH];             // combined attention weights
// fragment-layout bf16 hi/lo weights: [mb][kb][lane][8], kb count = 12
#define QKV_MB 36
#define PRJ_MB 12
#define NKB    12
__device__ __align__(16) __nv_bfloat16 g_wfqh[QKV_MB * NKB * 256];
__device__ __align__(16) __nv_bfloat16 g_wfql[QKV_MB * NKB * 256];
__device__ __align__(16) __nv_bfloat16 g_wfeh[BATCH * PRJ_MB * NKB * 256];
__device__ __align__(16) __nv_bfloat16 g_wfel[BATCH * PRJ_MB * NKB * 256];

// ---------------- weight split -> fragment layout + zero accumulators ------
__global__ void w_split(const float* __restrict__ wq)
{
    const int i = blockIdx.x * 256 + threadIdx.x;
    if (i < MQKV * KDIM) {
        const int m = i / KDIM, k = i % KDIM;
        const float x = wq[i];
        const __nv_bfloat16 h = __float2bfloat16(x);
        const __nv_bfloat16 l = __float2bfloat16(x - __bfloat162float(h));
        const int idx = ((m >> 4) * NKB + (k >> 4)) * 256 + frag_idx(m & 15, k & 15);
        g_wfqh[idx] = h;
        g_wfql[idx] = l;
    }
    if (i < BHN * CH * CH) g_S[i] = 0.f;
    if (i < BHN * 96)      g_norm[i] = 0.f;
}

// ---------------- tensor-core conv1x1 via mma.sync bf16 3-product split ----
// Y[b][m][p] = sum_k W_b[m][k] X_b[k][p].
// CTA owns a 64-pixel block; stages the FULL-K B tile (192x64 hi/lo) ONCE;
// A fragments come straight from L2 via LDG.128 (pre-packed frag layout).
// ZERO syncthreads in the mainloop.  8 warps (2m x 4n), warp tile 64x16.
#define GB_STRIDE 72
#define G_SMEM_BYTES (2 * 192 * GB_STRIDE * 2)      // 55296

__global__ __launch_bounds__(256, 3) void gemm_mma(
    const __nv_bfloat16* __restrict__ WfH, const __nv_bfloat16* __restrict__ WfL,
    const float* __restrict__ X, float* __restrict__ Y, int M, int nmt,
    long wstride, long xstride, long ystride)
{
    extern __shared__ __align__(16) __nv_bfloat16 sm[];
    __nv_bfloat16* sBh = sm;
    __nv_bfloat16* sBl = sm + 192 * GB_STRIDE;
    const uint32_t uBh = smem_u32(sBh), uBl = smem_u32(sBl);

    const int tid  = threadIdx.x;
    const int lane = tid & 31;
    const int wid  = tid >> 5;
    const int wm   = (wid >> 2) * 64;     // warp m offset (2 groups)
    const int wn   = (wid & 3) * 16;      // warp n offset (4 groups of 16)
    const int b    = blockIdx.z;
    const int p0   = blockIdx.x * 64;
    const __nv_bfloat16* WHb = WfH + (size_t)b * wstride;
    const __nv_bfloat16* WLb = WfL + (size_t)b * wstride;
    const float* Xb = X + (size_t)b * xstride;
    float*       Yb = Y + (size_t)b * ystride;

    // ---- B tile: full K=192 x 64 px, fp32 -> bf16 hi/lo, once ----
    #pragma unroll
    for (int i = 0; i < 12; ++i) {                  // 192 rows x 16 float4
        const int c  = tid + 256 * i;
        const int kk = c >> 4;
        const int p4 = (c & 15) * 4;
        const float4 v = *(const float4*)(Xb + (size_t)kk * HW + p0 + p4);
        u64 hp, lp;
        bsplit4(v, hp, lp);
        *(u64*)(sBh + kk * GB_STRIDE + p4) = hp;
        *(u64*)(sBl + kk * GB_STRIDE + p4) = lp;
    }
    __syncthreads();

    for (int mt = 0; mt < nmt; ++mt) {
        const int m0 = mt * 128;
        float acc[4][2][4];
        #pragma unroll
        for (int mi = 0; mi < 4; ++mi)
            #pragma unroll
            for (int ni = 0; ni < 2; ++ni)
                #pragma unroll
                for (int r = 0; r < 4; ++r) acc[mi][ni][r] = 0.f;

        #pragma unroll
        for (int kb = 0; kb < NKB; ++kb) {
            const int krow0 = kb * 16 + (lane & 15);
            uint32_t bh[2][2], bl[2][2];
            #pragma unroll
            for (int ni = 0; ni < 2; ++ni) {
                const uint32_t boffB =
                    (uint32_t)(krow0 * GB_STRIDE + wn + ni * 8) * 2;
                ldm_x2t(bh[ni], uBh + boffB);
                ldm_x2t(bl[ni], uBl + boffB);
            }
            #pragma unroll
            for (int mi = 0; mi < 4; ++mi) {
                const int m = m0 + wm + mi * 16;
                uint32_t ah[4] = {0u, 0u, 0u, 0u}, al[4] = {0u, 0u, 0u, 0u};
                if (m < M) {
                    const size_t fo =
                        (((size_t)(m >> 4) * NKB + kb) * 32 + lane) * 8;
                    *(uint4*)ah = *(const uint4*)(WHb + fo);
                    *(uint4*)al = *(const uint4*)(WLb + fo);
                }
                #pragma unroll
                for (int ni = 0; ni < 2; ++ni) {
                    mma_bf16(acc[mi][ni], ah, bh[ni]);   // Ah*Bh
                    mma_bf16(acc[mi][ni], ah, bl[ni]);   // Ah*Bl
                    mma_bf16(acc[mi][ni], al, bh[ni]);   // Al*Bh
                }
            }
        }

        const int g  = lane >> 2;
        const int tg = lane & 3;
        #pragma unroll
        for (int mi = 0; mi < 4; ++mi) {
            #pragma unroll
            for (int ni = 0; ni < 2; ++ni) {
                const int m = m0 + wm + mi * 16 + g;
                const int p = p0 + wn + ni * 8 + tg * 2;
                if (m < M)
                    *(float2*)(Yb + (size_t)m * HW + p) =
                        make_float2(acc[mi][ni][0], acc[mi][ni][1]);
                if (m + 8 < M)
                    *(float2*)(Yb + (size_t)(m + 8) * HW + p) =
                        make_float2(acc[mi][ni][2], acc[mi][ni][3]);
            }
        }
    }
}

// ---------------- depthwise 3x3, pad 1, smem-tiled 128x16 ------------------
#define DW_TH 16
__global__ __launch_bounds__(256) void dwconv3x3_t(
    const float* __restrict__ in, const float* __restrict__ wdw,
    float* __restrict__ out)
{
    const int bc = blockIdx.y;                  // 0..BATCH*MQKV-1
    const int h0 = blockIdx.x * DW_TH;
    const int ch = bc % MQKV;
    const float* base = in + (size_t)bc * HW;
    const int tid = threadIdx.x;

    __shared__ __align__(16) float st[DW_TH + 2][132];
    __shared__ float wsh[9];
    if (tid < 9) wsh[tid] = wdw[ch * 9 + tid];

    #pragma unroll
    for (int idx = tid; idx < 18 * 32; idx += 256) {
        const int r  = idx >> 5;
        const int c4 = (idx & 31) << 2;
        const int gh = h0 - 1 + r;
        float4 v = make_float4(0.f, 0.f, 0.f, 0.f);
        if (gh >= 0 && gh < HH) v = *(const float4*)(base + (size_t)gh * WW + c4);
        *(float4*)&st[r][c4] = v;
    }
    __syncthreads();

    const int w     = tid & 127;
    const int strip = tid >> 7;                 // 0 or 1
    const int hb    = strip * 8;                // local pixel rows hb..hb+7
    const bool wl = (w > 0), wr = (w < 127);
    const float w00 = wsh[0], w01 = wsh[1], w02 = wsh[2];
    const float w10 = wsh[3], w11 = wsh[4], w12 = wsh[5];
    const float w20 = wsh[6], w21 = wsh[7], w22 = wsh[8];

    float l0 = wl ? st[hb][w - 1] : 0.f;
    float m0 = st[hb][w];
    float r0 = wr ? st[hb][w + 1] : 0.f;
    float l1 = wl ? st[hb + 1][w - 1] : 0.f;
    float m1 = st[hb + 1][w];
    float r1 = wr ? st[hb + 1][w + 1] : 0.f;

    float* ob = out + (size_t)bc * HW + (size_t)(h0 + hb) * WW + w;
    #pragma unroll
    for (int rr = 0; rr < 8; ++rr) {
        const int sr = hb + rr + 2;
        const float l2 = wl ? st[sr][w - 1] : 0.f;
        const float m2 = st[sr][w];
        const float r2 = wr ? st[sr][w + 1] : 0.f;
        float s = w00 * l0;
        s = fmaf(w01, m0, s); s = fmaf(w02, r0, s);
        s = fmaf(w10, l1, s); s = fmaf(w11, m1, s); s = fmaf(w12, r1, s);
        s = fmaf(w20, l2, s); s = fmaf(w21, m2, s); s = fmaf(w22, r2, s);
        ob[(size_t)rr * WW] = s;
        l0 = l1; m0 = m1; r0 = r1;
        l1 = l2; m1 = m2; r1 = r2;
    }
}

// ---------------- S = q k^T (48x48) on tensor cores + scalar norms ---------
#define AP_STRIDE 72
__global__ __launch_bounds__(256) void attn_gram()
{
    __shared__ __align__(16) __nv_bfloat16 sZh[96 * AP_STRIDE];
    __shared__ __align__(16) __nv_bfloat16 sZl[96 * AP_STRIDE];
    const uint32_t uZh = smem_u32(sZh), uZl = smem_u32(sZl);

    const int tid  = threadIdx.x;
    const int lane = tid & 31;
    const int wid  = tid >> 5;
    const int wm   = (wid >> 1) * 16;       // 0,16,32 (warps 0-5)
    const int wn   = (wid & 1) * 24;        // 0,24
    const int bh   = blockIdx.x;
    const int b    = bh >> 2;
    const int hh   = bh & 3;
    const float* qbase = g_dw + ((size_t)b * MQKV + hh * CH) * HW;
    const float* kbase = g_dw + ((size_t)b * MQKV + DIM + hh * CH) * HW;
    const int n0 = blockIdx.y * 512;

    float acc[3][4];
    #pragma unroll
    for (int ni = 0; ni < 3; ++ni)
        #pragma unroll
        for (int r = 0; r < 4; ++r) acc[ni][r] = 0.f;
    float sq[6];
    #pragma unroll
    for (int i = 0; i < 6; ++i) sq[i] = 0.f;

    for (int t = 0; t < 8; ++t) {
        const int nb = n0 + t * 64;
        #pragma unroll
        for (int i = 0; i < 6; ++i) {
            const int c   = tid + 256 * i;
            const int row = c >> 4;
            const int c4  = (c & 15) << 2;
            const float* src = (row < 48)
                ? qbase + (size_t)row * HW + nb + c4
                : kbase + (size_t)(row - 48) * HW + nb + c4;
            const float4 v = *(const float4*)src;
            sq[i] = fmaf(v.x, v.x, sq[i]);
            sq[i] = fmaf(v.y, v.y, sq[i]);
            sq[i] = fmaf(v.z, v.z, sq[i]);
            sq[i] = fmaf(v.w, v.w, sq[i]);
            u64 hp, lp;
            bsplit4(v, hp, lp);
            *(u64*)(sZh + row * AP_STRIDE + c4) = hp;
            *(u64*)(sZl + row * AP_STRIDE + c4) = lp;
        }
        __syncthreads();

        if (wid < 6) {
            #pragma unroll
            for (int ks = 0; ks < 4; ++ks) {
                const int kk0 = ks * 16;
                const int arow = wm + (lane & 15);
                const uint32_t akcol = (uint32_t)(kk0 + ((lane >> 4) << 3));
                uint32_t ah[4], al[4];
                const uint32_t aoff =
                    (uint32_t)(arow * AP_STRIDE + akcol) * 2;
                ldm_x4(ah, uZh + aoff);
                ldm_x4(al, uZl + aoff);
                const int l16 = lane & 15;
                const int bn  = l16 & 7;
                const int bk  = kk0 + ((l16 >> 3) << 3);
                #pragma unroll
                for (int ni = 0; ni < 3; ++ni) {
                    uint32_t bfh[2], bfl[2];
                    const uint32_t boff =
                        (uint32_t)((48 + wn + ni * 8 + bn) * AP_STRIDE + bk) * 2;
                    ldm_x2(bfh, uZh + boff);
                    ldm_x2(bfl, uZl + boff);
                    mma_bf16(acc[ni], ah, bfh);
                    mma_bf16(acc[ni], ah, bfl);
                    mma_bf16(acc[ni], al, bfh);
                }
            }
        }
        __syncthreads();
    }

    #pragma unroll
    for (int i = 0; i < 6; ++i) {
        float s = sq[i];
        s += __shfl_xor_sync(0xffffffffu, s, 1);
        s += __shfl_xor_sync(0xffffffffu, s, 2);
        s += __shfl_xor_sync(0xffffffffu, s, 4);
        s += __shfl_xor_sync(0xffffffffu, s, 8);
        if ((lane & 15) == 0) {
            const int row = (tid >> 4) + 16 * i;
            atomicAdd(&g_norm[bh * 96 + row], s);
        }
    }

    if (wid < 6) {
        float* Sp = g_S + (size_t)bh * CH * CH;
        const int g  = lane >> 2;
        const int tg = lane & 3;
        #pragma unroll
        for (int ni = 0; ni < 3; ++ni) {
            const int m = wm + g;
            const int n = wn + ni * 8 + tg * 2;
            atomicAdd(&Sp[m * CH + n],           acc[ni][0]);
            atomicAdd(&Sp[m * CH + n + 1],       acc[ni][1]);
            atomicAdd(&Sp[(m + 8) * CH + n],     acc[ni][2]);
            atomicAdd(&Sp[(m + 8) * CH + n + 1], acc[ni][3]);
        }
    }
}

// ---------------- finalize: normalize, per-row topk/softmax, combine -------
// k values: int(48*rate) in IEEE double: {24, 32 (round-to-even), 36, 38}
__global__ void finalize_comb(const float* __restrict__ temperature,
                              const float* __restrict__ attn_w)
{
    const int bh = blockIdx.x;
    const int hh = bh & 3;
    const int i  = threadIdx.x;
    if (i >= CH) return;

    float a[CH];
    const float nq = fmaxf(sqrtf(g_norm[bh * 96 + i]), 1e-12f);
    const float tmp = temperature[hh];
    for (int j = 0; j < CH; ++j) {
        const float nk = fmaxf(sqrtf(g_norm[bh * 96 + 48 + j]), 1e-12f);
        a[j] = g_S[bh * CH * CH + i * CH + j] * tmp / (nq * nk);
    }

    int rank[CH];
    for (int j = 0; j < CH; ++j) {
        int r = 0;
        for (int l = 0; l < CH; ++l)
            if (a[l] > a[j] || (a[l] == a[j] && l < j)) r++;
        rank[j] = r;
    }

    float comb[CH];
    for (int j = 0; j < CH; ++j) comb[j] = 0.f;

    const int kvals[4] = {24, 32, 36, 38};
    for (int r = 0; r < 4; ++r) {
        const int kv = kvals[r];
        float m = -INFINITY;
        for (int j = 0; j < CH; ++j)
            if (rank[j] < kv) m = fmaxf(m, a[j]);
        float e[CH];
        float ssum = 0.f;
        for (int j = 0; j < CH; ++j) {
            e[j] = (rank[j] < kv) ? expf(a[j] - m) : 0.f;
            ssum += e[j];
        }
        const float wgt = attn_w[r] / ssum;
        for (int j = 0; j < CH; ++j) comb[j] = fmaf(e[j], wgt, comb[j]);
    }

    for (int j = 0; j < CH; ++j)
        g_comb[bh * CH * CH + i * CH + j] = comb[j];
}

// ---------------- W_eff = W_proj . blockdiag(comb), frag layout ------------
__global__ __launch_bounds__(192) void weff_compute(const float* __restrict__ wproj)
{
    const int bh = blockIdx.x;          // 0..15
    const int b  = bh >> 2;
    const int hh = bh & 3;
    const int o  = threadIdx.x;         // 0..191

    __shared__ float cs[CH][CH];
    for (int l = o; l < CH * CH; l += 192)
        cs[l / CH][l % CH] = g_comb[bh * CH * CH + l];
    __syncthreads();

    float wr[CH];
    #pragma unroll
    for (int c = 0; c < CH; ++c) wr[c] = wproj[o * KDIM + hh * CH + c];

    __nv_bfloat16* eh = g_wfeh + (size_t)b * PRJ_MB * NKB * 256;
    __nv_bfloat16* el = g_wfel + (size_t)b * PRJ_MB * NKB * 256;
    for (int d = 0; d < CH; ++d) {
        float s = 0.f;
        #pragma unroll
        for (int c = 0; c < CH; ++c) s = fmaf(wr[c], cs[c][d], s);
        const __nv_bfloat16 h = __float2bfloat16(s);
        const __nv_bfloat16 l = __float2bfloat16(s - __bfloat162float(h));
        const int k = hh * CH + d;
        const int idx = ((o >> 4) * NKB + (k >> 4)) * 256 + frag_idx(o & 15, k & 15);
        eh[idx] = h;
        el[idx] = l;
    }
}

// ---------------- launch ----------------------------------------------------
extern "C" void kernel_launch(void* const* d_in, const int* in_sizes, int n_in,
                              void* d_out, int out_size)
{
    const float* x           = (const float*)d_in[0];  // [4,192,128,128]
    const float* w_qkv       = (const float*)d_in[1];  // [576,192]
    const float* w_dw        = (const float*)d_in[2];  // [576,9]
    const float* w_proj      = (const float*)d_in[3];  // [192,192]
    const float* temperature = (const float*)d_in[4];  // [4]
    const float* attn_w      = (const float*)d_in[5];  // [4]
    float* out = (float*)d_out;

    float* qkv; cudaGetSymbolAddress((void**)&qkv, g_qkv);
    float* dw;  cudaGetSymbolAddress((void**)&dw,  g_dw);
    __nv_bfloat16* wfqh; cudaGetSymbolAddress((void**)&wfqh, g_wfqh);
    __nv_bfloat16* wfql; cudaGetSymbolAddress((void**)&wfql, g_wfql);
    __nv_bfloat16* wfeh; cudaGetSymbolAddress((void**)&wfeh, g_wfeh);
    __nv_bfloat16* wfel; cudaGetSymbolAddress((void**)&wfel, g_wfel);

    static bool attr_set = false;
    if (!attr_set) {
        cudaFuncSetAttribute(gemm_mma,
                             cudaFuncAttributeMaxDynamicSharedMemorySize,
                             G_SMEM_BYTES);
        attr_set = true;
    }

    // 0. split qkv weights -> bf16 hi/lo fragment layout + zero accumulators
    w_split<<<(MQKV * KDIM + 255) / 256, 256>>>(w_qkv);

    // 1. qkv = w_qkv @ x  (tensor cores; A frags from L2, no mainloop syncs)
    gemm_mma<<<dim3(HW / 64, 1, BATCH), 256, G_SMEM_BYTES>>>(
        wfqh, wfql, x, qkv, MQKV, 5, 0, (long)KDIM * HW, (long)MQKV * HW);

    // 2. depthwise 3x3 (smem-tiled, all 576 channels)
    dwconv3x3_t<<<dim3(HH / DW_TH, BATCH * MQKV), 256>>>(qkv, w_dw, dw);

    // 3. S = q.k^T (tensor cores, 48x48 only) + norms (scalar, fused)
    attn_gram<<<dim3(BHN, 32), 256>>>();

    // 4. combined attention weights (topk + softmax + weighted sum)
    finalize_comb<<<BHN, 64>>>(temperature, attn_w);

    // 5. W_eff[b] = W_proj . blockdiag(comb_b)  -> fragment layout
    weff_compute<<<BHN, 192>>>(w_proj);

    // 6. out = W_eff[b] @ v  (tensor cores, per-batch frag weights)
    gemm_mma<<<dim3(HW / 64, 1, BATCH), 256, G_SMEM_BYTES>>>(
        wfeh, wfel, dw + (size_t)2 * DIM * HW, out, DIM, 2,
        (long)PRJ_MB * NKB * 256, (long)MQKV * HW, (long)DIM * HW);
}